// round 1
// baseline (speedup 1.0000x reference)
#include <cuda_runtime.h>
#include <math.h>

#define HID   768
#define INTER 1536
#define DK    128
#define BATCH 4
#define SEQ   2048
#define MTOT  (BATCH*SEQ)          // 8192
#define NCOLS (2*INTER+DK)         // 3200
#define LOG512F 6.2383246250395075f

// ---------------- scratch (device globals; no allocation allowed) ----------
__device__ float g_u[(size_t)MTOT*INTER];
__device__ float g_v[(size_t)MTOT*INTER];
__device__ float g_q[(size_t)MTOT*DK];
__device__ float g_k[(size_t)MTOT*DK];
__device__ float g_A[(size_t)BATCH*SEQ*SEQ];
__device__ float g_t[(size_t)MTOT*INTER];

// ---------------- shared 128x128x8 SGEMM body ------------------------------
// 256 threads, each computes an 8x8 micro-tile. BT=true means the "B" operand
// is stored row-major as [N, K] (used for Q @ K^T).
template<bool BT>
__device__ __forceinline__ void gemm_body(const float* __restrict__ Ap, int lda,
                                          const float* __restrict__ Bp, int ldb,
                                          int K, int rowBase, int colBase,
                                          float acc[8][8])
{
    __shared__ __align__(16) float As[8][128];
    __shared__ __align__(16) float Bs[8][128];
    const int tid = threadIdx.x;
    const int tx = tid & 15, ty = tid >> 4;

    for (int k0 = 0; k0 < K; k0 += 8) {
        // A tile: 128 rows x 8 k, transposed into As[k][row]
        {
            int r = tid >> 1, c = (tid & 1) * 4;
            float4 v = *(const float4*)(Ap + (size_t)(rowBase + r) * lda + k0 + c);
            As[c + 0][r] = v.x; As[c + 1][r] = v.y;
            As[c + 2][r] = v.z; As[c + 3][r] = v.w;
        }
        if (BT) {
            // B stored [N, K]: load 128 n-rows x 8 k, transpose into Bs[k][n]
            int r = tid >> 1, c = (tid & 1) * 4;
            float4 v = *(const float4*)(Bp + (size_t)(colBase + r) * ldb + k0 + c);
            Bs[c + 0][r] = v.x; Bs[c + 1][r] = v.y;
            Bs[c + 2][r] = v.z; Bs[c + 3][r] = v.w;
        } else {
            // B stored [K, N]: 8 k-rows x 128 n, direct
            int kr = tid >> 5, c = (tid & 31) * 4;
            *(float4*)&Bs[kr][c] =
                *(const float4*)(Bp + (size_t)(k0 + kr) * ldb + colBase + c);
        }
        __syncthreads();

        #pragma unroll
        for (int kk = 0; kk < 8; kk++) {
            float4 a0 = *(const float4*)&As[kk][ty * 8];
            float4 a1 = *(const float4*)&As[kk][ty * 8 + 4];
            float4 b0 = *(const float4*)&Bs[kk][tx * 8];
            float4 b1 = *(const float4*)&Bs[kk][tx * 8 + 4];
            float av[8] = {a0.x, a0.y, a0.z, a0.w, a1.x, a1.y, a1.z, a1.w};
            float bv[8] = {b0.x, b0.y, b0.z, b0.w, b1.x, b1.y, b1.z, b1.w};
            #pragma unroll
            for (int i = 0; i < 8; i++)
                #pragma unroll
                for (int j = 0; j < 8; j++)
                    acc[i][j] += av[i] * bv[j];
        }
        __syncthreads();
    }
}

// ---------------- kernel 1: GEMM1 + SiLU + split ---------------------------
__global__ __launch_bounds__(256)
void k_gemm1(const float* __restrict__ H, const float* __restrict__ Wi,
             const float* __restrict__ qg, const float* __restrict__ kg)
{
    float acc[8][8] = {};
    const int rowBase = blockIdx.y * 128, colBase = blockIdx.x * 128;
    gemm_body<false>(H, HID, Wi, NCOLS, HID, rowBase, colBase, acc);

    const int tx = threadIdx.x & 15, ty = threadIdx.x >> 4;
    #pragma unroll
    for (int i = 0; i < 8; i++) {
        const int row = rowBase + ty * 8 + i;
        #pragma unroll
        for (int j = 0; j < 8; j++) {
            const int col = colBase + tx * 8 + j;
            float x = acc[i][j];
            float v = x / (1.0f + __expf(-x));   // SiLU
            if (col < INTER) {
                g_u[(size_t)row * INTER + col] = v;
            } else if (col < 2 * INTER) {
                g_v[(size_t)row * INTER + (col - INTER)] = v;
            } else {
                int c = col - 2 * INTER;
                g_q[(size_t)row * DK + c] = v * qg[c];
                g_k[(size_t)row * DK + c] = v * kg[c];
            }
        }
    }
}

// ---------------- kernel 2: Q @ K^T / sqrt(DK) -----------------------------
__global__ __launch_bounds__(256)
void k_qk()
{
    float acc[8][8] = {};
    const int b = blockIdx.z;
    const int rowBase = blockIdx.y * 128, colBase = blockIdx.x * 128;
    const float* Q  = g_q + (size_t)b * SEQ * DK;
    const float* Kp = g_k + (size_t)b * SEQ * DK;
    gemm_body<true>(Q, DK, Kp, DK, DK, rowBase, colBase, acc);

    float* Ab = g_A + (size_t)b * SEQ * SEQ;
    const float sc = 0.08838834764831845f;       // 1/sqrt(128)
    const int tx = threadIdx.x & 15, ty = threadIdx.x >> 4;
    #pragma unroll
    for (int i = 0; i < 8; i++) {
        const int row = rowBase + ty * 8 + i;
        #pragma unroll
        for (int j = 0; j < 8; j++) {
            const int col = colBase + tx * 8 + j;
            Ab[(size_t)row * SEQ + col] = acc[i][j] * sc;
        }
    }
}

// ---------------- kernel 3: masked, length-scaled softmax ------------------
__global__ __launch_bounds__(256)
void k_softmax(const int* __restrict__ mask)
{
    const int bm = blockIdx.x;
    const int b = bm >> 11;          // / SEQ
    const int m = bm & (SEQ - 1);
    const int tid = threadIdx.x;

    __shared__ float sdata[SEQ];
    __shared__ float red[256];

    // l = sum(mask[b])
    float ls = 0.f;
    for (int n = tid; n < SEQ; n += 256) ls += (float)mask[b * SEQ + n];
    red[tid] = ls; __syncthreads();
    for (int s = 128; s > 0; s >>= 1) {
        if (tid < s) red[tid] += red[tid + s];
        __syncthreads();
    }
    const float l = red[0];
    __syncthreads();
    const float scale = logf(fmaxf(l, 1.0f)) * (1.0f / LOG512F);

    float* row = g_A + (size_t)b * SEQ * SEQ + (size_t)m * SEQ;

    // pass 1: mask, scale, max
    float mx = -3.4e38f;
    for (int n = tid; n < SEQ; n += 256) {
        float a = row[n];
        if (mask[b * SEQ + n] == 0) a = -1e12f;
        a *= scale;
        sdata[n] = a;
        mx = fmaxf(mx, a);
    }
    red[tid] = mx; __syncthreads();
    for (int s = 128; s > 0; s >>= 1) {
        if (tid < s) red[tid] = fmaxf(red[tid], red[tid + s]);
        __syncthreads();
    }
    mx = red[0]; __syncthreads();

    // pass 2: exp + sum
    float sm = 0.f;
    for (int n = tid; n < SEQ; n += 256) {
        float e = __expf(sdata[n] - mx);
        sdata[n] = e;
        sm += e;
    }
    red[tid] = sm; __syncthreads();
    for (int s = 128; s > 0; s >>= 1) {
        if (tid < s) red[tid] += red[tid + s];
        __syncthreads();
    }
    const float inv = 1.0f / red[0];
    __syncthreads();

    // pass 3: normalize
    for (int n = tid; n < SEQ; n += 256) row[n] = sdata[n] * inv;
}

// ---------------- kernel 4: (A @ V) * u ------------------------------------
__global__ __launch_bounds__(256)
void k_av()
{
    float acc[8][8] = {};
    const int b = blockIdx.z;
    const int rowBase = blockIdx.y * 128, colBase = blockIdx.x * 128;
    const float* Ab = g_A + (size_t)b * SEQ * SEQ;
    const float* V  = g_v + (size_t)b * SEQ * INTER;
    gemm_body<false>(Ab, SEQ, V, INTER, SEQ, rowBase, colBase, acc);

    const int tx = threadIdx.x & 15, ty = threadIdx.x >> 4;
    #pragma unroll
    for (int i = 0; i < 8; i++) {
        const int row = rowBase + ty * 8 + i;
        const size_t base = ((size_t)(b * SEQ + row)) * INTER;
        #pragma unroll
        for (int j = 0; j < 8; j++) {
            const int col = colBase + tx * 8 + j;
            g_t[base + col] = g_u[base + col] * acc[i][j];
        }
    }
}

// ---------------- kernel 5: t @ Wo -> out ----------------------------------
__global__ __launch_bounds__(256)
void k_out(const float* __restrict__ Wo, float* __restrict__ out)
{
    float acc[8][8] = {};
    const int rowBase = blockIdx.y * 128, colBase = blockIdx.x * 128;
    gemm_body<false>(g_t, INTER, Wo, HID, INTER, rowBase, colBase, acc);

    const int tx = threadIdx.x & 15, ty = threadIdx.x >> 4;
    #pragma unroll
    for (int i = 0; i < 8; i++) {
        const int row = rowBase + ty * 8 + i;
        #pragma unroll
        for (int j = 0; j < 8; j++) {
            const int col = colBase + tx * 8 + j;
            out[(size_t)row * HID + col] = acc[i][j];
        }
    }
}

// ---------------- launch ----------------------------------------------------
extern "C" void kernel_launch(void* const* d_in, const int* in_sizes, int n_in,
                              void* d_out, int out_size)
{
    const float* h    = (const float*)d_in[0];
    const float* Wi   = (const float*)d_in[1];
    const float* Wo   = (const float*)d_in[2];
    const float* qg   = (const float*)d_in[3];
    const float* kg   = (const float*)d_in[4];
    const int*   mask = (const int*)d_in[5];
    float*       out  = (float*)d_out;

    k_gemm1<<<dim3(NCOLS / 128, MTOT / 128), 256>>>(h, Wi, qg, kg);
    k_qk<<<dim3(SEQ / 128, SEQ / 128, BATCH), 256>>>();
    k_softmax<<<BATCH * SEQ, 256>>>(mask);
    k_av<<<dim3(INTER / 128, SEQ / 128, BATCH), 256>>>();
    k_out<<<dim3(HID / 128, MTOT / 128), 256>>>(Wo, out);
}

// round 2
// speedup vs baseline: 3.9572x; 3.9572x over previous
#include <cuda_runtime.h>
#include <cuda_bf16.h>
#include <math.h>

#define HID   768
#define INTER 1536
#define DK    128
#define BATCH 4
#define SEQ   2048
#define MTOT  (BATCH*SEQ)          // 8192
#define NCOLS (2*INTER+DK)         // 3200
#define LOG512F 6.2383246250395075f

// ---------------- scratch (device globals) ---------------------------------
__device__ float g_u[(size_t)MTOT*INTER];
__device__ float g_v[(size_t)MTOT*INTER];
__device__ float g_q[(size_t)MTOT*DK];
__device__ float g_k[(size_t)MTOT*DK];
__device__ float g_A[(size_t)BATCH*SEQ*SEQ];
__device__ float g_t[(size_t)MTOT*INTER];

// ---------------- PTX helpers ----------------------------------------------
__device__ __forceinline__ void mma16816(float c[4], const unsigned a[4], const unsigned b[2]) {
    asm volatile(
        "mma.sync.aligned.m16n8k16.row.col.f32.bf16.bf16.f32 "
        "{%0,%1,%2,%3}, {%4,%5,%6,%7}, {%8,%9}, {%0,%1,%2,%3};\n"
        : "+f"(c[0]), "+f"(c[1]), "+f"(c[2]), "+f"(c[3])
        : "r"(a[0]), "r"(a[1]), "r"(a[2]), "r"(a[3]), "r"(b[0]), "r"(b[1]));
}
__device__ __forceinline__ void ldsm4(unsigned r[4], unsigned addr) {
    asm volatile("ldmatrix.sync.aligned.m8n8.x4.shared.b16 {%0,%1,%2,%3}, [%4];\n"
        : "=r"(r[0]), "=r"(r[1]), "=r"(r[2]), "=r"(r[3]) : "r"(addr));
}
__device__ __forceinline__ void ldsm4t(unsigned r[4], unsigned addr) {
    asm volatile("ldmatrix.sync.aligned.m8n8.x4.trans.shared.b16 {%0,%1,%2,%3}, [%4];\n"
        : "=r"(r[0]), "=r"(r[1]), "=r"(r[2]), "=r"(r[3]) : "r"(addr));
}

// split 8 fp32 -> hi/lo bf16 packed chunks (16B each)
__device__ __forceinline__ void cvt8(const float f[8], uint4& H, uint4& L) {
    unsigned h[8], l[8];
    #pragma unroll
    for (int j = 0; j < 8; j++) {
        __nv_bfloat16 hb = __float2bfloat16(f[j]);
        float hf = __bfloat162float(hb);
        __nv_bfloat16 lb = __float2bfloat16(f[j] - hf);
        h[j] = __bfloat16_as_ushort(hb);
        l[j] = __bfloat16_as_ushort(lb);
    }
    H.x = h[0] | (h[1] << 16); H.y = h[2] | (h[3] << 16);
    H.z = h[4] | (h[5] << 16); H.w = h[6] | (h[7] << 16);
    L.x = l[0] | (l[1] << 16); L.y = l[2] | (l[3] << 16);
    L.z = l[4] | (l[5] << 16); L.w = l[6] | (l[7] << 16);
}

// load a 128-row x 32-col fp32 tile into hi/lo bf16 smem, [row][k] layout,
// row stride 64B (4 chunks), chunk swizzle: c ^= (row>>1)&3
__device__ __forceinline__ void load_tile_128x32(const float* __restrict__ g, int ld,
                                                 uint4* shi, uint4* slo, int tid) {
    #pragma unroll
    for (int rnd = 0; rnd < 2; rnd++) {
        int e = (tid + rnd * 256) * 8;
        int row = e >> 5, k = e & 31;
        const float* p = g + (size_t)row * ld + k;
        float4 f0 = *(const float4*)p;
        float4 f1 = *(const float4*)(p + 4);
        float f[8] = {f0.x, f0.y, f0.z, f0.w, f1.x, f1.y, f1.z, f1.w};
        uint4 H, L; cvt8(f, H, L);
        int c = (k >> 3) ^ ((row >> 1) & 3);
        shi[row * 4 + c] = H;
        slo[row * 4 + c] = L;
    }
}

// load a 32-row x 128-col fp32 tile ([k][n]) into hi/lo bf16 smem,
// row stride 256B (16 chunks), chunk swizzle: c ^= k&7
__device__ __forceinline__ void load_tile_32x128(const float* __restrict__ g, int ld,
                                                 uint4* shi, uint4* slo, int tid) {
    #pragma unroll
    for (int rnd = 0; rnd < 2; rnd++) {
        int e = (tid + rnd * 256) * 8;
        int k = e >> 7, n = e & 127;
        const float* p = g + (size_t)k * ld + n;
        float4 f0 = *(const float4*)p;
        float4 f1 = *(const float4*)(p + 4);
        float f[8] = {f0.x, f0.y, f0.z, f0.w, f1.x, f1.y, f1.z, f1.w};
        uint4 H, L; cvt8(f, H, L);
        int c = (n >> 3) ^ (k & 7);
        shi[k * 16 + c] = H;
        slo[k * 16 + c] = L;
    }
}

// ---------------- bf16x3 tensor-core GEMM body -----------------------------
// 128x128 CTA tile, BK=32, 256 threads, warp grid 2(m) x 4(n), warp tile 64x32.
// BT=false: B is [K][N] row-major. BT=true: B is [N][K] row-major (Q@K^T).
template<bool BT>
__device__ __forceinline__ void mma_gemm(const float* __restrict__ Ap, int lda,
                                         const float* __restrict__ Bp, int ldb,
                                         int K, int rowBase, int colBase,
                                         float acc[4][4][4])
{
    __shared__ __align__(16) uint4 sAhi[512], sAlo[512], sBhi[512], sBlo[512];
    const int tid = threadIdx.x;
    const int lane = tid & 31, w = tid >> 5;
    const int wm = w >> 2, wn = w & 3;
    const unsigned baseAhi = (unsigned)__cvta_generic_to_shared(sAhi);
    const unsigned baseAlo = (unsigned)__cvta_generic_to_shared(sAlo);
    const unsigned baseBhi = (unsigned)__cvta_generic_to_shared(sBhi);
    const unsigned baseBlo = (unsigned)__cvta_generic_to_shared(sBlo);
    const int g = lane >> 3, i = lane & 7;

    for (int k0 = 0; k0 < K; k0 += 32) {
        load_tile_128x32(Ap + (size_t)rowBase * lda + k0, lda, sAhi, sAlo, tid);
        if (BT)
            load_tile_128x32(Bp + (size_t)colBase * ldb + k0, ldb, sBhi, sBlo, tid);
        else
            load_tile_32x128(Bp + (size_t)k0 * ldb + colBase, ldb, sBhi, sBlo, tid);
        __syncthreads();

        #pragma unroll
        for (int ks = 0; ks < 32; ks += 16) {
            unsigned aH[4][4], aL[4][4];
            #pragma unroll
            for (int mi = 0; mi < 4; mi++) {
                int mrow = wm * 64 + mi * 16 + (g & 1) * 8 + i;
                int ch = (ks >> 3) + (g >> 1);
                int off = mrow * 64 + ((ch ^ ((mrow >> 1) & 3)) << 4);
                ldsm4(aH[mi], baseAhi + off);
                ldsm4(aL[mi], baseAlo + off);
            }
            unsigned bH[4][2], bL[4][2];
            #pragma unroll
            for (int p = 0; p < 2; p++) {
                unsigned rh[4], rl[4];
                if (BT) {
                    int nrow = wn * 32 + p * 16 + (g >> 1) * 8 + i;
                    int ch = (ks >> 3) + (g & 1);
                    int off = nrow * 64 + ((ch ^ ((nrow >> 1) & 3)) << 4);
                    ldsm4(rh, baseBhi + off);
                    ldsm4(rl, baseBlo + off);
                } else {
                    int kr = ks + (g & 1) * 8 + i;
                    int nl = wn * 32 + p * 16 + (g >> 1) * 8;
                    int off = kr * 256 + ((((nl >> 3) ^ (kr & 7))) << 4);
                    ldsm4t(rh, baseBhi + off);
                    ldsm4t(rl, baseBlo + off);
                }
                bH[2*p][0] = rh[0]; bH[2*p][1] = rh[1];
                bH[2*p+1][0] = rh[2]; bH[2*p+1][1] = rh[3];
                bL[2*p][0] = rl[0]; bL[2*p][1] = rl[1];
                bL[2*p+1][0] = rl[2]; bL[2*p+1][1] = rl[3];
            }
            #pragma unroll
            for (int mi = 0; mi < 4; mi++)
                #pragma unroll
                for (int ng = 0; ng < 4; ng++) {
                    mma16816(acc[mi][ng], aH[mi], bH[ng]);
                    mma16816(acc[mi][ng], aH[mi], bL[ng]);
                    mma16816(acc[mi][ng], aL[mi], bH[ng]);
                }
        }
        __syncthreads();
    }
}

// epilogue coordinate helpers
#define EPI_SETUP() \
    const int lane = threadIdx.x & 31, w = threadIdx.x >> 5; \
    const int wm = w >> 2, wn = w & 3; \
    const int er = lane >> 2, ec = (lane & 3) * 2;

// ---------------- kernel 1: GEMM1 + SiLU + split ---------------------------
__global__ __launch_bounds__(256)
void k_gemm1(const float* __restrict__ H, const float* __restrict__ Wi,
             const float* __restrict__ qg, const float* __restrict__ kg)
{
    float acc[4][4][4] = {};
    const int rowBase = blockIdx.y * 128, colBase = blockIdx.x * 128;
    mma_gemm<false>(H, HID, Wi, NCOLS, HID, rowBase, colBase, acc);
    EPI_SETUP();
    #pragma unroll
    for (int mi = 0; mi < 4; mi++)
        #pragma unroll
        for (int ng = 0; ng < 4; ng++) {
            int r0 = rowBase + wm * 64 + mi * 16 + er;
            int c0 = colBase + wn * 32 + ng * 8 + ec;
            #pragma unroll
            for (int h = 0; h < 2; h++) {
                int row = r0 + h * 8;
                #pragma unroll
                for (int j = 0; j < 2; j++) {
                    int col = c0 + j;
                    float x = acc[mi][ng][h * 2 + j];
                    float v = x / (1.0f + __expf(-x));  // SiLU
                    if (col < INTER) {
                        g_u[(size_t)row * INTER + col] = v;
                    } else if (col < 2 * INTER) {
                        g_v[(size_t)row * INTER + (col - INTER)] = v;
                    } else {
                        int c = col - 2 * INTER;
                        g_q[(size_t)row * DK + c] = v * qg[c];
                        g_k[(size_t)row * DK + c] = v * kg[c];
                    }
                }
            }
        }
}

// ---------------- kernel 2: Q @ K^T / sqrt(DK) -----------------------------
__global__ __launch_bounds__(256)
void k_qk()
{
    float acc[4][4][4] = {};
    const int b = blockIdx.z;
    const int rowBase = blockIdx.y * 128, colBase = blockIdx.x * 128;
    mma_gemm<true>(g_q + (size_t)b * SEQ * DK, DK,
                   g_k + (size_t)b * SEQ * DK, DK, DK, rowBase, colBase, acc);
    float* Ab = g_A + (size_t)b * SEQ * SEQ;
    const float sc = 0.08838834764831845f;  // 1/sqrt(128)
    EPI_SETUP();
    #pragma unroll
    for (int mi = 0; mi < 4; mi++)
        #pragma unroll
        for (int ng = 0; ng < 4; ng++) {
            int r0 = rowBase + wm * 64 + mi * 16 + er;
            int c0 = colBase + wn * 32 + ng * 8 + ec;
            *(float2*)&Ab[(size_t)r0 * SEQ + c0] =
                make_float2(acc[mi][ng][0] * sc, acc[mi][ng][1] * sc);
            *(float2*)&Ab[(size_t)(r0 + 8) * SEQ + c0] =
                make_float2(acc[mi][ng][2] * sc, acc[mi][ng][3] * sc);
        }
}

// ---------------- kernel 3: masked, length-scaled softmax ------------------
__global__ __launch_bounds__(256)
void k_softmax(const int* __restrict__ mask)
{
    const int bm = blockIdx.x;
    const int b = bm >> 11;
    const int m = bm & (SEQ - 1);
    const int tid = threadIdx.x;

    __shared__ float sdata[SEQ];
    __shared__ float red[256];

    float ls = 0.f;
    for (int n = tid; n < SEQ; n += 256) ls += (float)mask[b * SEQ + n];
    red[tid] = ls; __syncthreads();
    for (int s = 128; s > 0; s >>= 1) {
        if (tid < s) red[tid] += red[tid + s];
        __syncthreads();
    }
    const float l = red[0];
    __syncthreads();
    const float scale = logf(fmaxf(l, 1.0f)) * (1.0f / LOG512F);

    float* row = g_A + (size_t)b * SEQ * SEQ + (size_t)m * SEQ;

    float mx = -3.4e38f;
    for (int n = tid; n < SEQ; n += 256) {
        float a = row[n];
        if (mask[b * SEQ + n] == 0) a = -1e12f;
        a *= scale;
        sdata[n] = a;
        mx = fmaxf(mx, a);
    }
    red[tid] = mx; __syncthreads();
    for (int s = 128; s > 0; s >>= 1) {
        if (tid < s) red[tid] = fmaxf(red[tid], red[tid + s]);
        __syncthreads();
    }
    mx = red[0]; __syncthreads();

    float sm = 0.f;
    for (int n = tid; n < SEQ; n += 256) {
        float e = __expf(sdata[n] - mx);
        sdata[n] = e;
        sm += e;
    }
    red[tid] = sm; __syncthreads();
    for (int s = 128; s > 0; s >>= 1) {
        if (tid < s) red[tid] += red[tid + s];
        __syncthreads();
    }
    const float inv = 1.0f / red[0];
    __syncthreads();

    for (int n = tid; n < SEQ; n += 256) row[n] = sdata[n] * inv;
}

// ---------------- kernel 4: (A @ V) * u ------------------------------------
__global__ __launch_bounds__(256)
void k_av()
{
    float acc[4][4][4] = {};
    const int b = blockIdx.z;
    const int rowBase = blockIdx.y * 128, colBase = blockIdx.x * 128;
    mma_gemm<false>(g_A + (size_t)b * SEQ * SEQ, SEQ,
                    g_v + (size_t)b * SEQ * INTER, INTER, SEQ,
                    rowBase, colBase, acc);
    EPI_SETUP();
    #pragma unroll
    for (int mi = 0; mi < 4; mi++)
        #pragma unroll
        for (int ng = 0; ng < 4; ng++) {
            int r0 = rowBase + wm * 64 + mi * 16 + er;
            int c0 = colBase + wn * 32 + ng * 8 + ec;
            #pragma unroll
            for (int h = 0; h < 2; h++) {
                int row = r0 + h * 8;
                size_t base = ((size_t)(b * SEQ + row)) * INTER + c0;
                float2 u2 = *(const float2*)&g_u[base];
                *(float2*)&g_t[base] =
                    make_float2(u2.x * acc[mi][ng][h * 2],
                                u2.y * acc[mi][ng][h * 2 + 1]);
            }
        }
}

// ---------------- kernel 5: t @ Wo -> out ----------------------------------
__global__ __launch_bounds__(256)
void k_out(const float* __restrict__ Wo, float* __restrict__ out)
{
    float acc[4][4][4] = {};
    const int rowBase = blockIdx.y * 128, colBase = blockIdx.x * 128;
    mma_gemm<false>(g_t, INTER, Wo, HID, INTER, rowBase, colBase, acc);
    EPI_SETUP();
    #pragma unroll
    for (int mi = 0; mi < 4; mi++)
        #pragma unroll
        for (int ng = 0; ng < 4; ng++) {
            int r0 = rowBase + wm * 64 + mi * 16 + er;
            int c0 = colBase + wn * 32 + ng * 8 + ec;
            *(float2*)&out[(size_t)r0 * HID + c0] =
                make_float2(acc[mi][ng][0], acc[mi][ng][1]);
            *(float2*)&out[(size_t)(r0 + 8) * HID + c0] =
                make_float2(acc[mi][ng][2], acc[mi][ng][3]);
        }
}

// ---------------- launch ----------------------------------------------------
extern "C" void kernel_launch(void* const* d_in, const int* in_sizes, int n_in,
                              void* d_out, int out_size)
{
    const float* h    = (const float*)d_in[0];
    const float* Wi   = (const float*)d_in[1];
    const float* Wo   = (const float*)d_in[2];
    const float* qg   = (const float*)d_in[3];
    const float* kg   = (const float*)d_in[4];
    const int*   mask = (const int*)d_in[5];
    float*       out  = (float*)d_out;

    k_gemm1<<<dim3(NCOLS / 128, MTOT / 128), 256>>>(h, Wi, qg, kg);
    k_qk<<<dim3(SEQ / 128, SEQ / 128, BATCH), 256>>>();
    k_softmax<<<BATCH * SEQ, 256>>>(mask);
    k_av<<<dim3(INTER / 128, SEQ / 128, BATCH), 256>>>();
    k_out<<<dim3(HID / 128, MTOT / 128), 256>>>(Wo, out);
}